// round 15
// baseline (speedup 1.0000x reference)
#include <cuda_runtime.h>
#include <math.h>
#include <stdint.h>

#define BB 4
#define SQ 2048
#define EE 1024
#define HH 16
#define DH 64
#define ROWS 16
#define KT 128

#define GM (BB*SQ)     // 8192
#define GN (3*EE)      // 3072
#define GK (EE)        // 1024

// GEMM tiling
#define TM 128
#define TN 128
#define TKS 32
#define PAD 36
#define ABUF (TM*PAD)

#define SCP 2052       // sc row pitch (mod 32 banks = 4)
#define KTP 8704       // K tile buffer stride (128*68)
#define VTP 8704       // V tile buffer stride (64*132 = 8448, padded)

// Scratch
__device__ float g_q[(size_t)BB * HH * SQ * DH];
__device__ float g_k[(size_t)BB * HH * SQ * DH];
__device__ float g_v[(size_t)BB * HH * DH * SQ];
__device__ float g_xr[(size_t)GM * GK];     // tf32-rounded x
__device__ float g_wr[(size_t)GN * GK];     // tf32-rounded W

__device__ __forceinline__ uint32_t f2tf32(float x) {
    uint32_t r;
    asm("cvt.rna.tf32.f32 %0, %1;" : "=r"(r) : "f"(x));
    return r;
}
__device__ __forceinline__ float tf32r(float x) { return __uint_as_float(f2tf32(x)); }

__device__ __forceinline__ void stcs4(float* p, float4 v) {
    asm volatile("st.global.cs.v4.f32 [%0], {%1,%2,%3,%4};\n"
                 :: "l"(p), "f"(v.x), "f"(v.y), "f"(v.z), "f"(v.w));
}

#define MMA_TF32(acc, a0, a1, a2, a3, b0, b1)                                \
    asm volatile(                                                            \
        "mma.sync.aligned.m16n8k8.row.col.f32.tf32.tf32.f32 "                \
        "{%0,%1,%2,%3}, {%4,%5,%6,%7}, {%8,%9}, {%0,%1,%2,%3};\n"            \
        : "+f"(acc[0]), "+f"(acc[1]), "+f"(acc[2]), "+f"(acc[3])             \
        : "r"(a0), "r"(a1), "r"(a2), "r"(a3), "r"(b0), "r"(b1))

#define CP_ASYNC16(dst, src) \
    asm volatile("cp.async.cg.shared.global [%0], [%1], 16;\n" :: "r"(dst), "l"(src))
#define CP_COMMIT()  asm volatile("cp.async.commit_group;\n" ::)
#define CP_WAIT(n)   asm volatile("cp.async.wait_group %0;\n" :: "n"(n))

// ---------------------------------------------------------------------------
// Pre-round input arrays to tf32.
// ---------------------------------------------------------------------------
__global__ __launch_bounds__(256) void round_tf32_kernel(
    const float* __restrict__ in, float* __restrict__ out, int n4)
{
    int i = blockIdx.x * 256 + threadIdx.x;
    if (i < n4) {
        float4 v = ((const float4*)in)[i];
        v.x = tf32r(v.x); v.y = tf32r(v.y); v.z = tf32r(v.z); v.w = tf32r(v.w);
        ((float4*)out)[i] = v;
    }
}

// ---------------------------------------------------------------------------
// QKV GEMM (TF32): qkv = xr @ Wr^T, scatter into g_k/g_q/g_v. (validated)
// ---------------------------------------------------------------------------
__global__ __launch_bounds__(256, 2) void qkv_gemm_tf32(
    const float* __restrict__ A, const float* __restrict__ W,
    float* __restrict__ gq, float* __restrict__ gk, float* __restrict__ gv)
{
    extern __shared__ float gs[];
    float* As = gs;
    float* Bs = gs + 2 * ABUF;

    const int tid  = threadIdx.x;
    const int lane = tid & 31;
    const int wid  = tid >> 5;
    const int wm   = wid & 3;
    const int wn   = wid >> 2;
    const int g    = lane >> 2;
    const int tig  = lane & 3;
    const int m0   = blockIdx.y * TM;
    const int n0   = blockIdx.x * TN;

    const uint32_t s_base = (uint32_t)__cvta_generic_to_shared(gs);

    float acc[2][8][4] = {};

    auto issue = [&](int s, int buf) {
        const int k0 = s * TKS;
        #pragma unroll
        for (int i = 0; i < 4; i++) {
            int c   = tid + i * 256;
            int row = c >> 3;
            int kc  = (c & 7) * 4;
            const float* srcA = A + (size_t)(m0 + row) * GK + k0 + kc;
            uint32_t dstA = s_base + (uint32_t)(buf * ABUF + row * PAD + kc) * 4u;
            CP_ASYNC16(dstA, srcA);
            const float* srcB = W + (size_t)(n0 + row) * GK + k0 + kc;
            uint32_t dstB = s_base + (uint32_t)(2 * ABUF * 4u) + (uint32_t)(buf * ABUF + row * PAD + kc) * 4u;
            CP_ASYNC16(dstB, srcB);
        }
        CP_COMMIT();
    };

    const int NS = GK / TKS;
    issue(0, 0);

    for (int s = 0; s < NS; s++) {
        const int cur = s & 1;
        CP_WAIT(0);
        __syncthreads();
        if (s + 1 < NS) issue(s + 1, cur ^ 1);

        const float* Ab = As + cur * ABUF + (wm * 32) * PAD;
        const float* Bb = Bs + cur * ABUF + (wn * 64) * PAD;

        #pragma unroll
        for (int kk = 0; kk < TKS; kk += 8) {
            uint32_t bf[8][2];
            #pragma unroll
            for (int nt = 0; nt < 8; nt++) {
                bf[nt][0] = __float_as_uint(Bb[(nt * 8 + g) * PAD + kk + tig]);
                bf[nt][1] = __float_as_uint(Bb[(nt * 8 + g) * PAD + kk + tig + 4]);
            }
            #pragma unroll
            for (int mt = 0; mt < 2; mt++) {
                uint32_t af[4];
                af[0] = __float_as_uint(Ab[(mt * 16 + g) * PAD     + kk + tig]);
                af[1] = __float_as_uint(Ab[(mt * 16 + g + 8) * PAD + kk + tig]);
                af[2] = __float_as_uint(Ab[(mt * 16 + g) * PAD     + kk + tig + 4]);
                af[3] = __float_as_uint(Ab[(mt * 16 + g + 8) * PAD + kk + tig + 4]);
                #pragma unroll
                for (int nt = 0; nt < 8; nt++)
                    MMA_TF32(acc[mt][nt], af[0], af[1], af[2], af[3], bf[nt][0], bf[nt][1]);
            }
        }
    }

    #pragma unroll
    for (int mt = 0; mt < 2; mt++) {
        #pragma unroll
        for (int nt = 0; nt < 8; nt++) {
            const int cc    = n0 + wn * 64 + nt * 8 + 2 * tig;
            const int chunk = cc >> 10;
            const int hd    = (cc & 1023) >> 6;
            const int d     = cc & 63;
            #pragma unroll
            for (int half = 0; half < 2; half++) {
                const int r = m0 + wm * 32 + mt * 16 + g + half * 8;
                const int b = r >> 11, srow = r & 2047;
                const float c0 = tf32r(acc[mt][nt][half * 2 + 0]);
                const float c1 = tf32r(acc[mt][nt][half * 2 + 1]);
                const size_t bh = (size_t)(b * HH + hd);
                if (chunk == 0) {
                    *(float2*)&gk[(bh * SQ + srow) * DH + d] = make_float2(c0, c1);
                } else if (chunk == 1) {
                    *(float2*)&gq[(bh * SQ + srow) * DH + d] = make_float2(c0, c1);
                } else {
                    gv[(bh * DH + d) * SQ + srow]     = c0;
                    gv[(bh * DH + d + 1) * SQ + srow] = c1;
                }
            }
        }
    }
}

// ---------------------------------------------------------------------------
// Fused causal ALiBi attention, TF32 MMA, R14 pipeline + fused row-max,
// split score MMA chains, pre-normalized tf32 probs in sc.
// One CTA per (b, h, 16-row query tile). 512 threads = 16 warps.
// ---------------------------------------------------------------------------
__global__ __launch_bounds__(512, 1) void attn_kernel(
    const float* __restrict__ gq, const float* __restrict__ gk,
    const float* __restrict__ gv, float* __restrict__ out,
    float* __restrict__ attn, int write_attn)
{
    extern __shared__ float smem[];
    float* sc   = smem;                    // 16 * SCP
    float* kq   = sc + ROWS * SCP;         // 2*KTP = 17408 floats
    float* qs   = kq + 2 * KTP;            // 16 * 68
    float* redm = qs + ROWS * 68;          // 16 warps * 16 rows
    float* rowstats = redm + 256;          // 16 row maxes

    const uint32_t s_kq = (uint32_t)__cvta_generic_to_shared(kq);

    const int i0 = (gridDim.x - 1 - blockIdx.x) * ROWS;   // longest tiles first
    const int h  = blockIdx.y;
    const int b  = blockIdx.z;
    const int tid  = threadIdx.x;
    const int lane = tid & 31;
    const int w    = tid >> 5;             // warp 0..15
    const int g    = lane >> 2;            // 0..7
    const int tig  = lane & 3;             // 0..3

    const size_t bh   = (size_t)(b * HH + h);
    const float slope = exp2f(-0.5f * (float)(h + 1));
    const float inv_scale = 1.0f / 32.0f;

    const int jend   = ((i0 + ROWS - 1) / 64 + 1) * 64;   // multiple of 64
    const int ntiles = (jend + KT - 1) / KT;

    // strength-reduced per-thread fill bases
    const float*  gk_base = gk + bh * SQ * DH + tid * 4;
    const uint32_t kdst0  = s_kq + (uint32_t)(((tid >> 4) * 68 + (tid & 15) * 4)) * 4u;
    const float*  gv_base = gv + (bh * DH + (tid >> 5)) * SQ + (tid & 31) * 4;
    const uint32_t vdst0  = s_kq + (uint32_t)(((tid >> 5) * 132 + (tid & 31) * 4)) * 4u;

    auto fill_k = [&](int t, int buf) {
        const int jt = t * KT;
        const int ktile = min(KT, jend - jt);
        const float* src = gk_base + jt * DH;
        uint32_t dst = kdst0 + (uint32_t)(buf * KTP) * 4u;
        const int n = (ktile == KT) ? 4 : 2;
        for (int i = 0; i < n; i++) {
            CP_ASYNC16(dst, src);
            dst += 32u * 68u * 4u;
            src += 2048;
        }
        CP_COMMIT();
    };
    auto fill_v = [&](int t, int buf) {
        const int jt = t * KT;
        const int ktile = min(KT, jend - jt);
        if (ktile == KT) {
            const float* src = gv_base + jt;
            uint32_t dst = vdst0 + (uint32_t)(buf * VTP) * 4u;
            #pragma unroll
            for (int i = 0; i < 4; i++) {
                CP_ASYNC16(dst, src);
                dst += 16u * 132u * 4u;
                src += 16 * SQ;
            }
        } else {
            for (int idx = tid; idx < 64 * 16; idx += 512) {
                int d = idx >> 4, jc = (idx & 15) * 4;
                CP_ASYNC16(s_kq + (uint32_t)(buf * VTP + d * 132 + jc) * 4u,
                           &gv[(bh * DH + d) * SQ + jt + jc]);
            }
        }
        CP_COMMIT();
    };

    fill_k(0, 0);

    // --- load Q (16 x 64), pre-rounded tf32 ---
    if (tid < 256) {
        int r = tid >> 4, dc = (tid & 15) * 4;
        float4 v = *(const float4*)&gq[(bh * SQ + i0 + r) * DH + dc];
        *(float4*)&qs[r * 68 + dc] = v;
    }
    __syncthreads();

    // --- preload Q fragments (rows g, g+8), raw bits ---
    uint32_t qa[8][4];
    #pragma unroll
    for (int kk = 0; kk < 8; kk++) {
        qa[kk][0] = __float_as_uint(qs[g * 68       + kk * 8 + tig]);
        qa[kk][1] = __float_as_uint(qs[(g + 8) * 68 + kk * 8 + tig]);
        qa[kk][2] = __float_as_uint(qs[g * 68       + kk * 8 + tig + 4]);
        qa[kk][3] = __float_as_uint(qs[(g + 8) * 68 + kk * 8 + tig + 4]);
    }

    const int gi0 = i0 + g, gi1 = i0 + g + 8;

    // ======================= scores (MMA, running max, split chains) ==========
    float tm0 = -INFINITY, tm1 = -INFINITY;

    for (int t = 0; t < ntiles; t++) {
        const int cur = t & 1;
        const int jt  = t * KT;
        const int ktile = min(KT, jend - jt);
        if (t + 1 < ntiles) { fill_k(t + 1, cur ^ 1); CP_WAIT(1); }
        else                { CP_WAIT(0); }
        __syncthreads();

        if (w * 8 < ktile) {
            const float* ktb = kq + cur * KTP + (w * 8 + g) * 68;
            float accA[4] = {}, accB[4] = {};
            #pragma unroll
            for (int kk = 0; kk < 4; kk++) {
                uint32_t b0 = __float_as_uint(ktb[kk * 8 + tig]);
                uint32_t b1 = __float_as_uint(ktb[kk * 8 + tig + 4]);
                MMA_TF32(accA, qa[kk][0], qa[kk][1], qa[kk][2], qa[kk][3], b0, b1);
                uint32_t c0 = __float_as_uint(ktb[(kk + 4) * 8 + tig]);
                uint32_t c1 = __float_as_uint(ktb[(kk + 4) * 8 + tig + 4]);
                MMA_TF32(accB, qa[kk+4][0], qa[kk+4][1], qa[kk+4][2], qa[kk+4][3], c0, c1);
            }
            const int j0 = jt + w * 8 + 2 * tig;
            float s00 = accA[0] + accB[0], s01 = accA[1] + accB[1];
            float s10 = accA[2] + accB[2], s11 = accA[3] + accB[3];
            float v00 = (j0     <= gi0) ? fmaf(slope, (float)(j0 - gi0),     s00 * inv_scale) : -INFINITY;
            float v01 = (j0 + 1 <= gi0) ? fmaf(slope, (float)(j0 + 1 - gi0), s01 * inv_scale) : -INFINITY;
            float v10 = (j0     <= gi1) ? fmaf(slope, (float)(j0 - gi1),     s10 * inv_scale) : -INFINITY;
            float v11 = (j0 + 1 <= gi1) ? fmaf(slope, (float)(j0 + 1 - gi1), s11 * inv_scale) : -INFINITY;
            *(float2*)&sc[g * SCP + j0]       = make_float2(v00, v01);
            *(float2*)&sc[(g + 8) * SCP + j0] = make_float2(v10, v11);
            tm0 = fmaxf(tm0, fmaxf(v00, v01));
            tm1 = fmaxf(tm1, fmaxf(v10, v11));
        }
        __syncthreads();
    }

    // prefetch first V tile; it lands while softmax runs
    fill_v(0, 0);

    // --- cross-warp row max (quad shuffle + smem reduce) ---
    #pragma unroll
    for (int o = 1; o <= 2; o <<= 1) {
        tm0 = fmaxf(tm0, __shfl_xor_sync(0xffffffffu, tm0, o));
        tm1 = fmaxf(tm1, __shfl_xor_sync(0xffffffffu, tm1, o));
    }
    if (tig == 0) {
        redm[w * 16 + g]     = tm0;
        redm[w * 16 + g + 8] = tm1;
    }
    __syncthreads();
    if (tid < 16) {
        float m = -INFINITY;
        #pragma unroll
        for (int p = 0; p < 16; p++) m = fmaxf(m, redm[p * 16 + tid]);
        rowstats[tid] = m;
    }
    __syncthreads();

    // ======================= softmax (warp w owns row w) =======================
    {
        const float rmax = rowstats[w];
        float* row = sc + w * SCP;
        float sum = 0.f;
        for (int j = lane * 4; j < jend; j += 128) {
            float4 v = *(const float4*)(row + j);
            v.x = __expf(v.x - rmax); v.y = __expf(v.y - rmax);
            v.z = __expf(v.z - rmax); v.w = __expf(v.w - rmax);
            *(float4*)(row + j) = v;
            sum += v.x + v.y + v.z + v.w;
        }
        #pragma unroll
        for (int o = 16; o; o >>= 1) sum += __shfl_xor_sync(0xffffffffu, sum, o);
        const float inv = 1.0f / sum;

        // normalize: write attn (fp32) + store tf32-rounded normalized probs to sc
        float* arow = write_attn ? (attn + (bh * SQ + i0 + w) * SQ) : nullptr;
        for (int j = lane * 4; j < jend; j += 128) {
            float4 v = *(const float4*)(row + j);
            v.x *= inv; v.y *= inv; v.z *= inv; v.w *= inv;
            if (write_attn) stcs4(arow + j, v);
            v.x = tf32r(v.x); v.y = tf32r(v.y); v.z = tf32r(v.z); v.w = tf32r(v.w);
            *(float4*)(row + j) = v;
        }
        if (write_attn) {
            const float4 z = make_float4(0.f, 0.f, 0.f, 0.f);
            for (int j = jend + lane * 4; j < SQ; j += 128)
                stcs4(arow + j, z);
        }
    }

    // ======================= PV (MMA, R14 pipeline, raw fragments) ============
    const int ks2 = w >> 1;
    const int ng  = w & 1;
    float pacc[4][4] = {};

    for (int t = 0; t < ntiles; t++) {
        const int cur = t & 1;
        const int jt  = t * KT;
        const int ktile = min(KT, jend - jt);
        __syncthreads();                      // prev-buf reads + sc writes visible
        if (t + 1 < ntiles) { fill_v(t + 1, cur ^ 1); CP_WAIT(1); }
        else                { CP_WAIT(0); }
        __syncthreads();

        const int kb2 = ks2 * 16;
        if (kb2 < ktile) {
            const float* vtb = kq + cur * VTP;
            #pragma unroll
            for (int kk2 = 0; kk2 < 2; kk2++) {
                const int kloc = kb2 + kk2 * 8;
                uint32_t af0 = __float_as_uint(sc[g * SCP       + jt + kloc + tig]);
                uint32_t af1 = __float_as_uint(sc[(g + 8) * SCP + jt + kloc + tig]);
                uint32_t af2 = __float_as_uint(sc[g * SCP       + jt + kloc + tig + 4]);
                uint32_t af3 = __float_as_uint(sc[(g + 8) * SCP + jt + kloc + tig + 4]);
                #pragma unroll
                for (int nt = 0; nt < 4; nt++) {
                    const int d = ng * 32 + nt * 8 + g;
                    uint32_t b0 = __float_as_uint(vtb[d * 132 + kloc + tig]);
                    uint32_t b1 = __float_as_uint(vtb[d * 132 + kloc + tig + 4]);
                    MMA_TF32(pacc[nt], af0, af1, af2, af3, b0, b1);
                }
            }
        }
    }

    // --- reduce partials across the 8 key-slab warps (overlay on kq) ---
    __syncthreads();
    float* red = kq;   // 7 * 16 * 64 floats
    if (ks2 > 0) {
        #pragma unroll
        for (int nt = 0; nt < 4; nt++) {
            const int col = ng * 32 + nt * 8 + 2 * tig;
            *(float2*)&red[((ks2 - 1) * 16 + g) * 64 + col]     = make_float2(pacc[nt][0], pacc[nt][1]);
            *(float2*)&red[((ks2 - 1) * 16 + g + 8) * 64 + col] = make_float2(pacc[nt][2], pacc[nt][3]);
        }
    }
    __syncthreads();
    if (ks2 == 0) {
        #pragma unroll
        for (int nt = 0; nt < 4; nt++) {
            const int col = ng * 32 + nt * 8 + 2 * tig;
            #pragma unroll
            for (int half = 0; half < 2; half++) {
                const int row = g + half * 8;
                float s0 = pacc[nt][half * 2 + 0];
                float s1 = pacc[nt][half * 2 + 1];
                #pragma unroll
                for (int p = 0; p < 7; p++) {
                    s0 += red[(p * 16 + row) * 64 + col];
                    s1 += red[(p * 16 + row) * 64 + col + 1];
                }
                *(float2*)&out[(size_t)(b * SQ + i0 + row) * EE + h * DH + col] =
                    make_float2(s0, s1);
            }
        }
    }
}

// ---------------------------------------------------------------------------
extern "C" void kernel_launch(void* const* d_in, const int* in_sizes, int n_in,
                              void* d_out, int out_size)
{
    const float* x = (const float*)d_in[0];
    const float* W = (const float*)d_in[1];
    float* out = (float*)d_out;

    const long out_elems  = (long)BB * SQ * EE;
    const long attn_elems = (long)BB * HH * SQ * SQ;
    int write_attn = ((long)out_size >= out_elems + attn_elems) ? 1 : 0;
    float* attn = write_attn ? (out + out_elems) : nullptr;

    float *gq, *gk, *gv, *xr, *wr;
    cudaGetSymbolAddress((void**)&gq, g_q);
    cudaGetSymbolAddress((void**)&gk, g_k);
    cudaGetSymbolAddress((void**)&gv, g_v);
    cudaGetSymbolAddress((void**)&xr, g_xr);
    cudaGetSymbolAddress((void**)&wr, g_wr);

    // Pre-round inputs to tf32
    {
        int n4x = GM * GK / 4;
        int n4w = GN * GK / 4;
        round_tf32_kernel<<<(n4x + 255) / 256, 256>>>(x, xr, n4x);
        round_tf32_kernel<<<(n4w + 255) / 256, 256>>>(W, wr, n4w);
    }

    // QKV projection (TF32 tensor cores, raw fragments)
    {
        int gemm_smem = 4 * ABUF * (int)sizeof(float);
        cudaFuncSetAttribute(qkv_gemm_tf32, cudaFuncAttributeMaxDynamicSharedMemorySize, gemm_smem);
        dim3 grid(GN / TN, GM / TM);
        qkv_gemm_tf32<<<grid, 256, gemm_smem>>>(xr, wr, gq, gk, gv);
    }

    // Fused attention
    {
        int smem_bytes = (ROWS * SCP + 2 * KTP + ROWS * 68 + 256 + 16) * (int)sizeof(float);
        cudaFuncSetAttribute(attn_kernel, cudaFuncAttributeMaxDynamicSharedMemorySize, smem_bytes);
        dim3 grid(SQ / ROWS, HH, BB);
        attn_kernel<<<grid, 512, smem_bytes>>>(gq, gk, gv, out, attn, write_attn);
    }
}

// round 16
// speedup vs baseline: 1.0374x; 1.0374x over previous
#include <cuda_runtime.h>
#include <math.h>
#include <stdint.h>

#define BB 4
#define SQ 2048
#define EE 1024
#define HH 16
#define DH 64
#define ROWS 16

#define GM (BB*SQ)     // 8192
#define GN (3*EE)      // 3072
#define GK (EE)        // 1024

// GEMM tiling
#define TM 128
#define TN 128
#define TKS 32
#define PAD 36
#define ABUF (TM*PAD)

#define SCP 2052       // sc row pitch (mod 32 banks = 4)

// Scratch: q [B,H,S,Dh]; k [B,H,S,Dh] d-permuted; v [B,H,Dh,S] key-permuted
__device__ float g_q[(size_t)BB * HH * SQ * DH];
__device__ float g_k[(size_t)BB * HH * SQ * DH];
__device__ float g_v[(size_t)BB * HH * DH * SQ];
__device__ float g_xr[(size_t)GM * GK];
__device__ float g_wr[(size_t)GN * GK];

__device__ __forceinline__ uint32_t f2tf32(float x) {
    uint32_t r;
    asm("cvt.rna.tf32.f32 %0, %1;" : "=r"(r) : "f"(x));
    return r;
}
__device__ __forceinline__ float tf32r(float x) { return __uint_as_float(f2tf32(x)); }
__device__ __forceinline__ uint32_t fu(float x) { return __float_as_uint(x); }

__device__ __forceinline__ void stcs4(float* p, float4 v) {
    asm volatile("st.global.cs.v4.f32 [%0], {%1,%2,%3,%4};\n"
                 :: "l"(p), "f"(v.x), "f"(v.y), "f"(v.z), "f"(v.w));
}

#define MMA_TF32(acc, a0, a1, a2, a3, b0, b1)                                \
    asm volatile(                                                            \
        "mma.sync.aligned.m16n8k8.row.col.f32.tf32.tf32.f32 "                \
        "{%0,%1,%2,%3}, {%4,%5,%6,%7}, {%8,%9}, {%0,%1,%2,%3};\n"            \
        : "+f"(acc[0]), "+f"(acc[1]), "+f"(acc[2]), "+f"(acc[3])             \
        : "r"(a0), "r"(a1), "r"(a2), "r"(a3), "r"(b0), "r"(b1))

#define CP_ASYNC16(dst, src) \
    asm volatile("cp.async.cg.shared.global [%0], [%1], 16;\n" :: "r"(dst), "l"(src))
#define CP_COMMIT()  asm volatile("cp.async.commit_group;\n" ::)
#define CP_WAIT(n)   asm volatile("cp.async.wait_group %0;\n" :: "n"(n))

// ---------------------------------------------------------------------------
__global__ __launch_bounds__(256) void round_tf32_kernel(
    const float* __restrict__ in, float* __restrict__ out, int n4)
{
    int i = blockIdx.x * 256 + threadIdx.x;
    if (i < n4) {
        float4 v = ((const float4*)in)[i];
        v.x = tf32r(v.x); v.y = tf32r(v.y); v.z = tf32r(v.z); v.w = tf32r(v.w);
        ((float4*)out)[i] = v;
    }
}

// ---------------------------------------------------------------------------
// QKV GEMM (TF32): qkv = xr @ Wr^T; scatter with fragment-friendly permutes.
// K: d' = (d&3)*16 + (d>>2).  V: key' = (k&~15) + (k&3)*4 + ((k>>2)&3).
// ---------------------------------------------------------------------------
__global__ __launch_bounds__(256, 2) void qkv_gemm_tf32(
    const float* __restrict__ A, const float* __restrict__ W,
    float* __restrict__ gq, float* __restrict__ gk, float* __restrict__ gv)
{
    extern __shared__ float gs[];
    float* As = gs;
    float* Bs = gs + 2 * ABUF;

    const int tid  = threadIdx.x;
    const int lane = tid & 31;
    const int wid  = tid >> 5;
    const int wm   = wid & 3;
    const int wn   = wid >> 2;
    const int g    = lane >> 2;
    const int tig  = lane & 3;
    const int m0   = blockIdx.y * TM;
    const int n0   = blockIdx.x * TN;

    const uint32_t s_base = (uint32_t)__cvta_generic_to_shared(gs);

    float acc[2][8][4] = {};

    auto issue = [&](int s, int buf) {
        const int k0 = s * TKS;
        #pragma unroll
        for (int i = 0; i < 4; i++) {
            int c   = tid + i * 256;
            int row = c >> 3;
            int kc  = (c & 7) * 4;
            const float* srcA = A + (size_t)(m0 + row) * GK + k0 + kc;
            uint32_t dstA = s_base + (uint32_t)(buf * ABUF + row * PAD + kc) * 4u;
            CP_ASYNC16(dstA, srcA);
            const float* srcB = W + (size_t)(n0 + row) * GK + k0 + kc;
            uint32_t dstB = s_base + (uint32_t)(2 * ABUF * 4u) + (uint32_t)(buf * ABUF + row * PAD + kc) * 4u;
            CP_ASYNC16(dstB, srcB);
        }
        CP_COMMIT();
    };

    const int NS = GK / TKS;
    issue(0, 0);

    for (int s = 0; s < NS; s++) {
        const int cur = s & 1;
        CP_WAIT(0);
        __syncthreads();
        if (s + 1 < NS) issue(s + 1, cur ^ 1);

        const float* Ab = As + cur * ABUF + (wm * 32) * PAD;
        const float* Bb = Bs + cur * ABUF + (wn * 64) * PAD;

        #pragma unroll
        for (int kk = 0; kk < TKS; kk += 8) {
            uint32_t bf[8][2];
            #pragma unroll
            for (int nt = 0; nt < 8; nt++) {
                bf[nt][0] = fu(Bb[(nt * 8 + g) * PAD + kk + tig]);
                bf[nt][1] = fu(Bb[(nt * 8 + g) * PAD + kk + tig + 4]);
            }
            #pragma unroll
            for (int mt = 0; mt < 2; mt++) {
                uint32_t af[4];
                af[0] = fu(Ab[(mt * 16 + g) * PAD     + kk + tig]);
                af[1] = fu(Ab[(mt * 16 + g + 8) * PAD + kk + tig]);
                af[2] = fu(Ab[(mt * 16 + g) * PAD     + kk + tig + 4]);
                af[3] = fu(Ab[(mt * 16 + g + 8) * PAD + kk + tig + 4]);
                #pragma unroll
                for (int nt = 0; nt < 8; nt++)
                    MMA_TF32(acc[mt][nt], af[0], af[1], af[2], af[3], bf[nt][0], bf[nt][1]);
            }
        }
    }

    #pragma unroll
    for (int mt = 0; mt < 2; mt++) {
        #pragma unroll
        for (int nt = 0; nt < 8; nt++) {
            const int cc    = n0 + wn * 64 + nt * 8 + 2 * tig;
            const int chunk = cc >> 10;
            const int hd    = (cc & 1023) >> 6;
            const int d     = cc & 63;         // even
            #pragma unroll
            for (int half = 0; half < 2; half++) {
                const int r = m0 + wm * 32 + mt * 16 + g + half * 8;
                const int b = r >> 11, srow = r & 2047;
                const float c0 = tf32r(acc[mt][nt][half * 2 + 0]);
                const float c1 = tf32r(acc[mt][nt][half * 2 + 1]);
                const size_t bh = (size_t)(b * HH + hd);
                if (chunk == 0) {
                    // K: permute d' = (d&3)*16 + (d>>2)
                    float* kr = gk + (bh * SQ + srow) * DH;
                    kr[((d & 3) * 16) + (d >> 2)]             = c0;
                    kr[(((d + 1) & 3) * 16) + ((d + 1) >> 2)] = c1;
                } else if (chunk == 1) {
                    *(float2*)&gq[(bh * SQ + srow) * DH + d] = make_float2(c0, c1);
                } else {
                    // V^T: permute key within 16-block
                    const int sp = (srow & ~15) + (srow & 3) * 4 + ((srow >> 2) & 3);
                    gv[(bh * DH + d) * SQ + sp]       = c0;
                    gv[(bh * DH + d + 1) * SQ + sp]   = c1;
                }
            }
        }
    }
}

// ---------------------------------------------------------------------------
// Fused causal ALiBi attention, TF32 MMA, direct-LDG B-fragments (no K/V smem
// staging, barrier-free score/PV streams). One CTA per (b,h,16 rows), 16 warps.
// ---------------------------------------------------------------------------
__global__ __launch_bounds__(512, 1) void attn_kernel(
    const float* __restrict__ gq, const float* __restrict__ gk,
    const float* __restrict__ gv, float* __restrict__ out,
    float* __restrict__ attn, int write_attn)
{
    extern __shared__ float smem[];
    float* sc       = smem;                  // 16 * SCP
    float* qs       = sc + ROWS * SCP;       // 16 * 68
    float* redm     = qs + ROWS * 68;        // 256
    float* rowstats = redm + 256;            // 16
    float* red      = rowstats + 16;         // 7*16*64 = 7168

    const int i0 = (gridDim.x - 1 - blockIdx.x) * ROWS;   // longest tiles first
    const int h  = blockIdx.y;
    const int b  = blockIdx.z;
    const int tid  = threadIdx.x;
    const int lane = tid & 31;
    const int w    = tid >> 5;
    const int g    = lane >> 2;
    const int tig  = lane & 3;

    const size_t bh   = (size_t)(b * HH + h);
    const float slope = exp2f(-0.5f * (float)(h + 1));
    const float inv_scale = 1.0f / 32.0f;

    const int jend = ((i0 + ROWS - 1) / 64 + 1) * 64;

    // --- load Q (16 x 64) ---
    if (tid < 256) {
        int r = tid >> 4, dc = (tid & 15) * 4;
        float4 v = *(const float4*)&gq[(bh * SQ + i0 + r) * DH + dc];
        *(float4*)&qs[r * 68 + dc] = v;
    }
    __syncthreads();

    uint32_t qa[8][4];
    #pragma unroll
    for (int kk = 0; kk < 8; kk++) {
        qa[kk][0] = fu(qs[g * 68       + kk * 8 + tig]);
        qa[kk][1] = fu(qs[(g + 8) * 68 + kk * 8 + tig]);
        qa[kk][2] = fu(qs[g * 68       + kk * 8 + tig + 4]);
        qa[kk][3] = fu(qs[(g + 8) * 68 + kk * 8 + tig + 4]);
    }

    const int gi0 = i0 + g, gi1 = i0 + g + 8;

    // ======================= scores (direct LDG, barrier-free) ================
    float tm0 = -INFINITY, tm1 = -INFINITY;
    {
        // thread reads K'[row = key + g][tig*16 .. +15] (d-permuted layout)
        const float* kbase = gk + (bh * SQ + g) * DH + tig * 16;
        int j0 = w * 8;
        float4 n0v, n1v, n2v, n3v;
        if (j0 < jend) {
            const float* kp = kbase + (size_t)j0 * DH;
            n0v = *(const float4*)kp;       n1v = *(const float4*)(kp + 4);
            n2v = *(const float4*)(kp + 8); n3v = *(const float4*)(kp + 12);
        }
        for (; j0 < jend; j0 += 128) {
            float4 c0 = n0v, c1 = n1v, c2 = n2v, c3 = n3v;
            const int jn = j0 + 128;
            if (jn < jend) {
                const float* kp = kbase + (size_t)jn * DH;
                n0v = *(const float4*)kp;       n1v = *(const float4*)(kp + 4);
                n2v = *(const float4*)(kp + 8); n3v = *(const float4*)(kp + 12);
            }
            float accA[4] = {}, accB[4] = {};
            MMA_TF32(accA, qa[0][0], qa[0][1], qa[0][2], qa[0][3], fu(c0.x), fu(c0.y));
            MMA_TF32(accB, qa[4][0], qa[4][1], qa[4][2], qa[4][3], fu(c2.x), fu(c2.y));
            MMA_TF32(accA, qa[1][0], qa[1][1], qa[1][2], qa[1][3], fu(c0.z), fu(c0.w));
            MMA_TF32(accB, qa[5][0], qa[5][1], qa[5][2], qa[5][3], fu(c2.z), fu(c2.w));
            MMA_TF32(accA, qa[2][0], qa[2][1], qa[2][2], qa[2][3], fu(c1.x), fu(c1.y));
            MMA_TF32(accB, qa[6][0], qa[6][1], qa[6][2], qa[6][3], fu(c3.x), fu(c3.y));
            MMA_TF32(accA, qa[3][0], qa[3][1], qa[3][2], qa[3][3], fu(c1.z), fu(c1.w));
            MMA_TF32(accB, qa[7][0], qa[7][1], qa[7][2], qa[7][3], fu(c3.z), fu(c3.w));

            const int jc = j0 + 2 * tig;
            float s00 = accA[0] + accB[0], s01 = accA[1] + accB[1];
            float s10 = accA[2] + accB[2], s11 = accA[3] + accB[3];
            float v00 = (jc     <= gi0) ? fmaf(slope, (float)(jc - gi0),     s00 * inv_scale) : -INFINITY;
            float v01 = (jc + 1 <= gi0) ? fmaf(slope, (float)(jc + 1 - gi0), s01 * inv_scale) : -INFINITY;
            float v10 = (jc     <= gi1) ? fmaf(slope, (float)(jc - gi1),     s10 * inv_scale) : -INFINITY;
            float v11 = (jc + 1 <= gi1) ? fmaf(slope, (float)(jc + 1 - gi1), s11 * inv_scale) : -INFINITY;
            *(float2*)&sc[g * SCP + jc]       = make_float2(v00, v01);
            *(float2*)&sc[(g + 8) * SCP + jc] = make_float2(v10, v11);
            tm0 = fmaxf(tm0, fmaxf(v00, v01));
            tm1 = fmaxf(tm1, fmaxf(v10, v11));
        }
    }

    // --- cross-warp row max ---
    #pragma unroll
    for (int o = 1; o <= 2; o <<= 1) {
        tm0 = fmaxf(tm0, __shfl_xor_sync(0xffffffffu, tm0, o));
        tm1 = fmaxf(tm1, __shfl_xor_sync(0xffffffffu, tm1, o));
    }
    if (tig == 0) {
        redm[w * 16 + g]     = tm0;
        redm[w * 16 + g + 8] = tm1;
    }
    __syncthreads();
    if (tid < 16) {
        float m = -INFINITY;
        #pragma unroll
        for (int p = 0; p < 16; p++) m = fmaxf(m, redm[p * 16 + tid]);
        rowstats[tid] = m;
    }
    __syncthreads();

    // ======================= softmax (warp w owns row w) =======================
    {
        const float rmax = rowstats[w];
        float* row = sc + w * SCP;
        float sum = 0.f;
        for (int j = lane * 4; j < jend; j += 128) {
            float4 v = *(const float4*)(row + j);
            v.x = __expf(v.x - rmax); v.y = __expf(v.y - rmax);
            v.z = __expf(v.z - rmax); v.w = __expf(v.w - rmax);
            *(float4*)(row + j) = v;
            sum += v.x + v.y + v.z + v.w;
        }
        #pragma unroll
        for (int o = 16; o; o >>= 1) sum += __shfl_xor_sync(0xffffffffu, sum, o);
        const float inv = 1.0f / sum;

        float* arow = write_attn ? (attn + (bh * SQ + i0 + w) * SQ) : nullptr;
        for (int j = lane * 4; j < jend; j += 128) {
            float4 v = *(const float4*)(row + j);
            v.x *= inv; v.y *= inv; v.z *= inv; v.w *= inv;
            if (write_attn) stcs4(arow + j, v);
            v.x = tf32r(v.x); v.y = tf32r(v.y); v.z = tf32r(v.z); v.w = tf32r(v.w);
            *(float4*)(row + j) = v;
        }
        if (write_attn) {
            const float4 z = make_float4(0.f, 0.f, 0.f, 0.f);
            for (int j = jend + lane * 4; j < SQ; j += 128)
                stcs4(arow + j, z);
        }
    }
    __syncthreads();   // sc probs visible to all PV warps

    // ======================= PV (direct LDG, barrier-free) ====================
    const int ks2 = w >> 1;
    const int ng  = w & 1;
    float pacc[4][4] = {};
    {
        // thread reads V'[d = ng*32 + nt*8 + g][kb + tig*4 .. +3] (key-permuted)
        const float* vbase = gv + (bh * DH + ng * 32 + g) * SQ + tig * 4;
        int kb = ks2 * 16;
        float4 nv[4];
        if (kb < jend) {
            #pragma unroll
            for (int nt = 0; nt < 4; nt++)
                nv[nt] = *(const float4*)(vbase + (size_t)(nt * 8) * SQ + kb);
        }
        for (; kb < jend; kb += 128) {
            float4 cv[4] = {nv[0], nv[1], nv[2], nv[3]};
            const int kn = kb + 128;
            if (kn < jend) {
                #pragma unroll
                for (int nt = 0; nt < 4; nt++)
                    nv[nt] = *(const float4*)(vbase + (size_t)(nt * 8) * SQ + kn);
            }
            uint32_t a00 = fu(sc[g * SCP       + kb + tig]);
            uint32_t a01 = fu(sc[(g + 8) * SCP + kb + tig]);
            uint32_t a02 = fu(sc[g * SCP       + kb + tig + 4]);
            uint32_t a03 = fu(sc[(g + 8) * SCP + kb + tig + 4]);
            uint32_t a10 = fu(sc[g * SCP       + kb + 8 + tig]);
            uint32_t a11 = fu(sc[(g + 8) * SCP + kb + 8 + tig]);
            uint32_t a12 = fu(sc[g * SCP       + kb + 12 + tig]);
            uint32_t a13 = fu(sc[(g + 8) * SCP + kb + 12 + tig]);
            #pragma unroll
            for (int nt = 0; nt < 4; nt++) {
                MMA_TF32(pacc[nt], a00, a01, a02, a03, fu(cv[nt].x), fu(cv[nt].y));
                MMA_TF32(pacc[nt], a10, a11, a12, a13, fu(cv[nt].z), fu(cv[nt].w));
            }
        }
    }

    // --- reduce partials across the 8 key-slab warps ---
    __syncthreads();
    if (ks2 > 0) {
        #pragma unroll
        for (int nt = 0; nt < 4; nt++) {
            const int col = ng * 32 + nt * 8 + 2 * tig;
            *(float2*)&red[((ks2 - 1) * 16 + g) * 64 + col]     = make_float2(pacc[nt][0], pacc[nt][1]);
            *(float2*)&red[((ks2 - 1) * 16 + g + 8) * 64 + col] = make_float2(pacc[nt][2], pacc[nt][3]);
        }
    }
    __syncthreads();
    if (ks2 == 0) {
        #pragma unroll
        for (int nt = 0; nt < 4; nt++) {
            const int col = ng * 32 + nt * 8 + 2 * tig;
            #pragma unroll
            for (int half = 0; half < 2; half++) {
                const int row = g + half * 8;
                float s0 = pacc[nt][half * 2 + 0];
                float s1 = pacc[nt][half * 2 + 1];
                #pragma unroll
                for (int p = 0; p < 7; p++) {
                    s0 += red[(p * 16 + row) * 64 + col];
                    s1 += red[(p * 16 + row) * 64 + col + 1];
                }
                *(float2*)&out[(size_t)(b * SQ + i0 + row) * EE + h * DH + col] =
                    make_float2(s0, s1);
            }
        }
    }
}

// ---------------------------------------------------------------------------
extern "C" void kernel_launch(void* const* d_in, const int* in_sizes, int n_in,
                              void* d_out, int out_size)
{
    const float* x = (const float*)d_in[0];
    const float* W = (const float*)d_in[1];
    float* out = (float*)d_out;

    const long out_elems  = (long)BB * SQ * EE;
    const long attn_elems = (long)BB * HH * SQ * SQ;
    int write_attn = ((long)out_size >= out_elems + attn_elems) ? 1 : 0;
    float* attn = write_attn ? (out + out_elems) : nullptr;

    float *gq, *gk, *gv, *xr, *wr;
    cudaGetSymbolAddress((void**)&gq, g_q);
    cudaGetSymbolAddress((void**)&gk, g_k);
    cudaGetSymbolAddress((void**)&gv, g_v);
    cudaGetSymbolAddress((void**)&xr, g_xr);
    cudaGetSymbolAddress((void**)&wr, g_wr);

    // Pre-round inputs to tf32
    {
        int n4x = GM * GK / 4;
        int n4w = GN * GK / 4;
        round_tf32_kernel<<<(n4x + 255) / 256, 256>>>(x, xr, n4x);
        round_tf32_kernel<<<(n4w + 255) / 256, 256>>>(W, wr, n4w);
    }

    // QKV projection (TF32 tensor cores)
    {
        int gemm_smem = 4 * ABUF * (int)sizeof(float);
        cudaFuncSetAttribute(qkv_gemm_tf32, cudaFuncAttributeMaxDynamicSharedMemorySize, gemm_smem);
        dim3 grid(GN / TN, GM / TM);
        qkv_gemm_tf32<<<grid, 256, gemm_smem>>>(xr, wr, gq, gk, gv);
    }

    // Fused attention (direct-LDG fragments)
    {
        int smem_bytes = (ROWS * SCP + ROWS * 68 + 256 + 16 + 7 * 16 * 64) * (int)sizeof(float);
        cudaFuncSetAttribute(attn_kernel, cudaFuncAttributeMaxDynamicSharedMemorySize, smem_bytes);
        dim3 grid(SQ / ROWS, HH, BB);
        attn_kernel<<<grid, 512, smem_bytes>>>(gq, gk, gv, out, attn, write_attn);
    }
}